// round 17
// baseline (speedup 1.0000x reference)
#include <cuda_runtime.h>
#include <cstdint>

// Problem constants
#define Nn 4
#define Cc 64
#define Hh 192
#define Ww 192
#define OUTC 3
#define HOUT 768
#define WOUT 768
#define KTOT 576
#define NCOLS 48
#define HIDDEN 256
#define M2 1728

// Conv tile: 16x16 pixels = 256 GEMM rows, 48 cols, K = 576 (k' = pos*64 + c)
#define TP 16
#define HALO 18
#define HALO_POS (HALO * HALO)     // 324
#define HSTRIDE 68                 // floats per halo position (64 ch + 4 pad)
#define BSTRIDE 580                // floats per weight column (576 + 4 pad)

#define SW_FLOATS (NCOLS * BSTRIDE)                    // 27840
#define HALO_OFF  SW_FLOATS
#define SMEM_FLOATS (SW_FLOATS + HALO_POS * HSTRIDE)   // 49872
#define SMEM_BYTES (SMEM_FLOATS * 4)                   // 199488

// Dynamic weights as GEMM B: g_w[col][k'], col = sp*3+o, k' = pos*64+c, tf32-rounded
__device__ __align__(16) float g_w[NCOLS * KTOT];

// ---------------------------------------------------------------------------
// Stage 1: Pos2Weight MLP -> g_w[col][pos*64+c], tf32-rounded (rna).
// ---------------------------------------------------------------------------
__global__ void mlp_kernel(const float* __restrict__ W1, const float* __restrict__ b1,
                           const float* __restrict__ W2, const float* __restrict__ b2) {
    __shared__ float hidden[HIDDEN];
    const int sp = blockIdx.x;
    const int chunk = blockIdx.y;
    const int tid = threadIdx.x;

    const float p0 = 0.25f;
    const float p1 = (float)(sp >> 2) * 0.25f;
    const float p2 = (float)(sp & 3) * 0.25f;

    float h = fmaf(p0, W1[tid], fmaf(p1, W1[256 + tid], fmaf(p2, W1[512 + tid], b1[tid])));
    hidden[tid] = fmaxf(h, 0.0f);
    __syncthreads();

    if (tid < 216) {
        const int m = chunk * 216 + tid;
        float sum = b2[m];
        #pragma unroll 8
        for (int j = 0; j < HIDDEN; ++j)
            sum = fmaf(hidden[j], W2[j * M2 + m], sum);
        const int k = m / 3;
        const int o = m - k * 3;
        const int c = k / 9;
        const int pos = k - c * 9;
        uint32_t tv;
        asm("cvt.rna.tf32.f32 %0, %1;" : "=r"(tv) : "f"(sum));
        ((uint32_t*)g_w)[(sp * 3 + o) * KTOT + pos * 64 + c] = tv;
    }
}

// ---------------------------------------------------------------------------
// tf32 warp MMA: D[16x8] += A[16x8] * B[8x8]   (row.col)
// ---------------------------------------------------------------------------
__device__ __forceinline__ void mma_tf32(float* d, const uint32_t* a, const uint32_t* b) {
    asm volatile(
        "mma.sync.aligned.m16n8k8.row.col.f32.tf32.tf32.f32 "
        "{%0,%1,%2,%3}, {%4,%5,%6,%7}, {%8,%9}, {%0,%1,%2,%3};"
        : "+f"(d[0]), "+f"(d[1]), "+f"(d[2]), "+f"(d[3])
        : "r"(a[0]), "r"(a[1]), "r"(a[2]), "r"(a[3]), "r"(b[0]), "r"(b[1]));
}

// ---------------------------------------------------------------------------
// Stage 2: tf32 mma.sync GEMM + pixel shuffle.
// grid (12, 12, 4), 512 threads (16 warps, 4 warps/SMSP).
// Warp (wm = wid>>1, wn = wid&1): pixel rows {2wm, 2wm+1} x cols [wn*24, wn*24+24).
// Per k8-step: 8 A LDS + 6 B LDS (conflict-free), 6 MMAs; fragments double-buffered
// with one-step prefetch to break the LDS->MMA dependency chain.
// ---------------------------------------------------------------------------
__global__ void __launch_bounds__(512, 1)
conv_kernel(const float* __restrict__ in, float* __restrict__ out) {
    extern __shared__ float smem[];
    float* sw = smem;                      // [48][580]
    float* hs = smem + HALO_OFF;           // [324][68]

    const int tw = blockIdx.x, th = blockIdx.y, n = blockIdx.z;
    const int tid = threadIdx.x;
    const int wid = tid >> 5, lane = tid & 31;
    const int g = lane >> 2, t = lane & 3;
    const int wm = wid >> 1, wn = wid & 1;

    // --- B: copy g_w [48][576] -> smem [48][580] (float4) ---
    {
        const float4* gw4 = (const float4*)g_w;
        for (int i = tid; i < NCOLS * 144; i += 512) {
            const int col = i / 144, q = i - col * 144;
            *(float4*)(sw + col * BSTRIDE + q * 4) = gw4[i];
        }
    }
    // --- halo: [pos = lh*18+lw][c], stride 68, zero-padded, tf32-rounded ---
    {
        const int gh0 = th * TP - 1, gw0 = tw * TP - 1;
        const float* inb = in + (size_t)n * Cc * Hh * Ww;
        uint32_t* hu = (uint32_t*)hs;
        for (int i = tid; i < Cc * HALO_POS; i += 512) {
            const int c = i / HALO_POS, r = i - c * HALO_POS;
            const int lh = r / HALO, lw = r - lh * HALO;
            const int gh = gh0 + lh, gw = gw0 + lw;
            float v = 0.0f;
            if ((unsigned)gh < (unsigned)Hh && (unsigned)gw < (unsigned)Ww)
                v = inb[(c * Hh + gh) * Ww + gw];
            uint32_t tv;
            asm("cvt.rna.tf32.f32 %0, %1;" : "=r"(tv) : "f"(v));
            hu[r * HSTRIDE + c] = tv;
        }
    }
    __syncthreads();

    // Lane-fixed base pointers (conflict-free: addr ≡ 4g + t mod 32 banks).
    const uint32_t* hb0 = (const uint32_t*)hs + ((2 * wm) * HALO + g) * HSTRIDE + t;
    const uint32_t* hb1 = hb0 + HALO * HSTRIDE;                 // pixel row +1
    const uint32_t* bb  = (const uint32_t*)sw + (wn * 24 + g) * BSTRIDE + t;

    float acc[2][3][4];
    #pragma unroll
    for (int mt = 0; mt < 2; ++mt)
        #pragma unroll
        for (int nt = 0; nt < 3; ++nt)
            #pragma unroll
            for (int r = 0; r < 4; ++r) acc[mt][nt][r] = 0.0f;

    uint32_t A[2][8], B[2][6];     // double-buffered fragments

    // fragment loader: offA = (di*18+dj)*HSTRIDE + c0, offB = pos*64 + c0
    #define LDFRAG(buf, offA, offB) do {                                   \
        const uint32_t* _ha = hb0 + (offA);                                \
        const uint32_t* _hb = hb1 + (offA);                                \
        A[buf][0] = _ha[0];             A[buf][1] = _ha[8 * HSTRIDE];      \
        A[buf][2] = _ha[4];             A[buf][3] = _ha[8 * HSTRIDE + 4];  \
        A[buf][4] = _hb[0];             A[buf][5] = _hb[8 * HSTRIDE];      \
        A[buf][6] = _hb[4];             A[buf][7] = _hb[8 * HSTRIDE + 4];  \
        const uint32_t* _bb = bb + (offB);                                 \
        B[buf][0] = _bb[0];                 B[buf][1] = _bb[4];            \
        B[buf][2] = _bb[8 * BSTRIDE];       B[buf][3] = _bb[8 * BSTRIDE + 4];   \
        B[buf][4] = _bb[16 * BSTRIDE];      B[buf][5] = _bb[16 * BSTRIDE + 4];  \
    } while (0)

    LDFRAG(0, 0, 0);

    #pragma unroll 1
    for (int pos = 0; pos < 9; ++pos) {
        const int di = pos / 3, dj = pos - di * 3;
        const int baseA = (di * HALO + dj) * HSTRIDE;
        const int baseB = pos * 64;
        const int np = pos + 1;
        const int ndi = np / 3, ndj = np - ndi * 3;
        const int nbaseA = (ndi * HALO + ndj) * HSTRIDE;   // only used if pos < 8
        const int nbaseB = np * 64;

        #pragma unroll
        for (int cb = 0; cb < 8; ++cb) {
            const int cur = cb & 1, nxt = cur ^ 1;
            if (cb < 7) {
                LDFRAG(nxt, baseA + (cb + 1) * 8, baseB + (cb + 1) * 8);
            } else if (pos < 8) {
                LDFRAG(nxt, nbaseA, nbaseB);
            }
            #pragma unroll
            for (int mt = 0; mt < 2; ++mt)
                #pragma unroll
                for (int nt = 0; nt < 3; ++nt)
                    mma_tf32(acc[mt][nt], A[cur] + mt * 4, B[cur] + nt * 2);
        }
    }
    #undef LDFRAG

    __syncthreads();           // smem free; reuse as staging
    float* stage = smem;       // [192 rows][64 floats] = 48 KB

    // --- scatter accumulators into pixel-shuffled staging layout ---
    // row = o*64 + hl*4 + si ; col = wl*4 + sj   (hl,wl = tile-local pixel)
    #pragma unroll
    for (int mt = 0; mt < 2; ++mt) {
        const int hl = 2 * wm + mt;
        #pragma unroll
        for (int nt = 0; nt < 3; ++nt) {
            #pragma unroll
            for (int r = 0; r < 4; ++r) {
                const int wl = g + ((r >> 1) << 3);                  // g or g+8
                const int col = wn * 24 + nt * 8 + 2 * t + (r & 1);  // = sp*3 + o
                const int sp = col / 3;
                const int o  = col - sp * 3;
                const int si = sp >> 2, sj = sp & 3;
                stage[(o * 64 + hl * 4 + si) * 64 + wl * 4 + sj] = acc[mt][nt][r];
            }
        }
    }
    __syncthreads();

    // --- coalesced float4 stores: each stage row = 64 contiguous output floats ---
    {
        float* outb = out + (size_t)n * OUTC * HOUT * WOUT;
        const float4* st4 = (const float4*)stage;
        #pragma unroll
        for (int v = tid; v < 192 * 16; v += 512) {
            const int flat = v * 4;
            const int row = flat >> 6, cc = flat & 63;
            const int o = row >> 6, rr = row & 63;
            const int hl = rr >> 2, si = rr & 3;
            const int gh = (th * TP + hl) * 4 + si;
            const int gw = tw * 64 + cc;
            *(float4*)(outb + ((size_t)o * HOUT + gh) * WOUT + gw) = st4[v];
        }
    }
}

// ---------------------------------------------------------------------------
extern "C" void kernel_launch(void* const* d_in, const int* in_sizes, int n_in,
                              void* d_out, int out_size) {
    const float* x  = (const float*)d_in[0];
    const float* W1 = (const float*)d_in[1];
    const float* b1 = (const float*)d_in[2];
    const float* W2 = (const float*)d_in[3];
    const float* b2 = (const float*)d_in[4];
    float* out = (float*)d_out;

    mlp_kernel<<<dim3(16, 8), 256>>>(W1, b1, W2, b2);

    cudaFuncSetAttribute(conv_kernel, cudaFuncAttributeMaxDynamicSharedMemorySize, SMEM_BYTES);
    conv_kernel<<<dim3(Ww / TP, Hh / TP, Nn), 512, SMEM_BYTES>>>(x, out);
}